// round 1
// baseline (speedup 1.0000x reference)
#include <cuda_runtime.h>
#include <cuda_bf16.h>

#define DIMQ 256
#define M_TILE 64
#define NTHR 256

// SMEM: xs [u=64][e=64] float4, ys [v=64][e=64] float4, wt 4 paths x [v=64][w=64] float
// = 64*64*16 * 2 + 4*4096*4 = 196608 bytes
#define SMEM_BYTES 196608

__global__ void __launch_bounds__(NTHR, 1)
fc_tp_kernel(const float* __restrict__ e1x, const float* __restrict__ e1y,
             const float* __restrict__ e2x, const float* __restrict__ e2y,
             const float* __restrict__ W1_000, const float* __restrict__ W1_110,
             const float* __restrict__ W1_011, const float* __restrict__ W1_101,
             const float* __restrict__ W2_000, const float* __restrict__ W2_110,
             const float* __restrict__ W2_011, const float* __restrict__ W2_101,
             float* __restrict__ out, int E)
{
    extern __shared__ float smem[];
    float4* xs  = reinterpret_cast<float4*>(smem);   // [u][e]
    float4* ys  = xs + 64 * 64;                      // [v][e]
    float4* wt4 = ys + 64 * 64;                      // 4 x 1024 float4: [path][v][w/4]

    const float INV_SQRT3 = 0.57735026918962576f;
    const float ALPHA0    = 0.011048543456039806f;   // 1/sqrt(2*64*64)
    const float OUT1S     = ALPHA0 * INV_SQRT3;

    const int tid = threadIdx.x;
    const int te  = tid >> 4;   // 0..15 -> edges te*4..te*4+3
    const int tw  = tid & 15;   // 0..15 -> w = tw*4..tw*4+3
    const int e0  = blockIdx.x * M_TILE;

    float acc0[4][4];
    float acc1[4][3][4];
    #pragma unroll
    for (int e = 0; e < 4; ++e) {
        #pragma unroll
        for (int w = 0; w < 4; ++w) acc0[e][w] = 0.f;
        #pragma unroll
        for (int i = 0; i < 3; ++i)
            #pragma unroll
            for (int w = 0; w < 4; ++w) acc1[e][i][w] = 0.f;
    }

    #pragma unroll 1
    for (int tp = 0; tp < 2; ++tp) {
        const float* xg = tp ? e2x : e1x;
        const float* yg = tp ? e2y : e1y;
        const float* Wa = tp ? W2_000 : W1_000;
        const float* Wb = tp ? W2_110 : W1_110;
        const float* Wc = tp ? W2_011 : W1_011;
        const float* Wd = tp ? W2_101 : W1_101;

        __syncthreads();  // guard previous iteration's ys/xs reads
        for (int idx = tid; idx < 64 * 64; idx += NTHR) {
            const int e  = idx >> 6;
            const int u  = idx & 63;
            const int ge = e0 + e;
            float4 vx = make_float4(0.f, 0.f, 0.f, 0.f);
            float4 vy = vx;
            if (ge < E) {
                const float* xr = xg + (size_t)ge * DIMQ;
                vx = make_float4(xr[u], xr[64 + 3 * u], xr[65 + 3 * u], xr[66 + 3 * u]);
                const float* yr = yg + (size_t)ge * DIMQ;
                vy = make_float4(yr[u], yr[64 + 3 * u], yr[65 + 3 * u], yr[66 + 3 * u]);
            }
            xs[u * 64 + e] = vx;
            ys[u * 64 + e] = vy;
        }
        __syncthreads();

        #pragma unroll 1
        for (int u = 0; u < 64; ++u) {
            __syncthreads();  // guard previous u's wt reads
            {
                const float4* sa = reinterpret_cast<const float4*>(Wa + (size_t)u * 4096);
                const float4* sb = reinterpret_cast<const float4*>(Wb + (size_t)u * 4096);
                const float4* sc = reinterpret_cast<const float4*>(Wc + (size_t)u * 4096);
                const float4* sd = reinterpret_cast<const float4*>(Wd + (size_t)u * 4096);
                #pragma unroll
                for (int k = 0; k < 4; ++k) {
                    const int idx = tid + k * NTHR;    // 0..1023
                    wt4[idx] = sa[idx];
                    float4 t = sb[idx];
                    t.x *= INV_SQRT3; t.y *= INV_SQRT3; t.z *= INV_SQRT3; t.w *= INV_SQRT3;
                    wt4[1024 + idx] = t;               // INV_SQRT3 folded into W110
                    wt4[2048 + idx] = sc[idx];
                    wt4[3072 + idx] = sd[idx];
                }
            }
            __syncthreads();

            float4 xv[4];
            #pragma unroll
            for (int e = 0; e < 4; ++e) xv[e] = xs[u * 64 + te * 4 + e];

            #pragma unroll 2
            for (int v = 0; v < 64; ++v) {
                const float4 b000 = wt4[v * 16 + tw];
                const float4 b110 = wt4[1024 + v * 16 + tw];
                const float4 b011 = wt4[2048 + v * 16 + tw];
                const float4 b101 = wt4[3072 + v * 16 + tw];
                const float4* yrow = ys + v * 64 + te * 4;
                #pragma unroll
                for (int e = 0; e < 4; ++e) {
                    const float4 yv = yrow[e];
                    const float s000 = xv[e].x * yv.x;
                    const float s110 = xv[e].y * yv.y + xv[e].z * yv.z + xv[e].w * yv.w;
                    acc0[e][0] += s000 * b000.x + s110 * b110.x;
                    acc0[e][1] += s000 * b000.y + s110 * b110.y;
                    acc0[e][2] += s000 * b000.z + s110 * b110.z;
                    acc0[e][3] += s000 * b000.w + s110 * b110.w;
                    const float a0 = xv[e].x * yv.y;   // x0 * y1_i
                    const float a1 = xv[e].x * yv.z;
                    const float a2 = xv[e].x * yv.w;
                    const float c0 = xv[e].y * yv.x;   // x1_i * y0
                    const float c1 = xv[e].z * yv.x;
                    const float c2 = xv[e].w * yv.x;
                    acc1[e][0][0] += a0 * b011.x + c0 * b101.x;
                    acc1[e][0][1] += a0 * b011.y + c0 * b101.y;
                    acc1[e][0][2] += a0 * b011.z + c0 * b101.z;
                    acc1[e][0][3] += a0 * b011.w + c0 * b101.w;
                    acc1[e][1][0] += a1 * b011.x + c1 * b101.x;
                    acc1[e][1][1] += a1 * b011.y + c1 * b101.y;
                    acc1[e][1][2] += a1 * b011.z + c1 * b101.z;
                    acc1[e][1][3] += a1 * b011.w + c1 * b101.w;
                    acc1[e][2][0] += a2 * b011.x + c2 * b101.x;
                    acc1[e][2][1] += a2 * b011.y + c2 * b101.y;
                    acc1[e][2][2] += a2 * b011.z + c2 * b101.z;
                    acc1[e][2][3] += a2 * b011.w + c2 * b101.w;
                }
            }
        }
    }

    #pragma unroll
    for (int e = 0; e < 4; ++e) {
        const int ge = e0 + te * 4 + e;
        if (ge < E) {
            float* o = out + (size_t)ge * DIMQ;
            #pragma unroll
            for (int w = 0; w < 4; ++w) {
                const int wg = tw * 4 + w;
                o[wg] = ALPHA0 * acc0[e][w];
                o[64 + wg * 3 + 0] = OUT1S * acc1[e][0][w];
                o[64 + wg * 3 + 1] = OUT1S * acc1[e][1][w];
                o[64 + wg * 3 + 2] = OUT1S * acc1[e][2][w];
            }
        }
    }
}

extern "C" void kernel_launch(void* const* d_in, const int* in_sizes, int n_in,
                              void* d_out, int out_size) {
    const float* e1x    = (const float*)d_in[0];
    const float* e1y    = (const float*)d_in[1];
    const float* e2x    = (const float*)d_in[2];
    const float* e2y    = (const float*)d_in[3];
    const float* W1_000 = (const float*)d_in[4];
    const float* W1_110 = (const float*)d_in[5];
    const float* W1_011 = (const float*)d_in[6];
    const float* W1_101 = (const float*)d_in[7];
    const float* W2_000 = (const float*)d_in[8];
    const float* W2_110 = (const float*)d_in[9];
    const float* W2_011 = (const float*)d_in[10];
    const float* W2_101 = (const float*)d_in[11];
    float* out = (float*)d_out;

    const int E = in_sizes[0] / DIMQ;
    const int grid = (E + M_TILE - 1) / M_TILE;

    cudaFuncSetAttribute(fc_tp_kernel,
                         cudaFuncAttributeMaxDynamicSharedMemorySize, SMEM_BYTES);
    fc_tp_kernel<<<grid, NTHR, SMEM_BYTES>>>(
        e1x, e1y, e2x, e2y,
        W1_000, W1_110, W1_011, W1_101,
        W2_000, W2_110, W2_011, W2_101,
        out, E);
}

// round 2
// speedup vs baseline: 1.0008x; 1.0008x over previous
#include <cuda_runtime.h>
#include <cuda_bf16.h>

#define DIMQ 256
#define M_TILE 64
#define NTHR 256

// SMEM: xs [u=64][e=64] float4, ys [v=64][e=64] float4, wt 4 paths x [v=64][w=64] float
// = 64*64*16 * 2 + 4*4096*4 = 196608 bytes
#define SMEM_BYTES 196608

__global__ void __launch_bounds__(NTHR, 1)
fc_tp_kernel(const float* __restrict__ e1x, const float* __restrict__ e1y,
             const float* __restrict__ e2x, const float* __restrict__ e2y,
             const float* __restrict__ W1_000, const float* __restrict__ W1_110,
             const float* __restrict__ W1_011, const float* __restrict__ W1_101,
             const float* __restrict__ W2_000, const float* __restrict__ W2_110,
             const float* __restrict__ W2_011, const float* __restrict__ W2_101,
             float* __restrict__ out, int E)
{
    extern __shared__ float smem[];
    float4* xs  = reinterpret_cast<float4*>(smem);   // [u][e]
    float4* ys  = xs + 64 * 64;                      // [v][e]
    float4* wt4 = ys + 64 * 64;                      // 4 x 1024 float4: [path][v][w/4]

    const float INV_SQRT3 = 0.57735026918962576f;
    const float ALPHA0    = 0.011048543456039806f;   // 1/sqrt(2*64*64)
    const float OUT1S     = ALPHA0 * INV_SQRT3;

    const int tid = threadIdx.x;
    const int te  = tid >> 4;   // 0..15 -> edges te*4..te*4+3
    const int tw  = tid & 15;   // 0..15 -> w = tw*4..tw*4+3
    const int e0  = blockIdx.x * M_TILE;

    float acc0[4][4];
    float acc1[4][3][4];
    #pragma unroll
    for (int e = 0; e < 4; ++e) {
        #pragma unroll
        for (int w = 0; w < 4; ++w) acc0[e][w] = 0.f;
        #pragma unroll
        for (int i = 0; i < 3; ++i)
            #pragma unroll
            for (int w = 0; w < 4; ++w) acc1[e][i][w] = 0.f;
    }

    #pragma unroll 1
    for (int tp = 0; tp < 2; ++tp) {
        const float* xg = tp ? e2x : e1x;
        const float* yg = tp ? e2y : e1y;
        const float* Wa = tp ? W2_000 : W1_000;
        const float* Wb = tp ? W2_110 : W1_110;
        const float* Wc = tp ? W2_011 : W1_011;
        const float* Wd = tp ? W2_101 : W1_101;

        __syncthreads();  // guard previous iteration's ys/xs reads
        for (int idx = tid; idx < 64 * 64; idx += NTHR) {
            const int e  = idx >> 6;
            const int u  = idx & 63;
            const int ge = e0 + e;
            float4 vx = make_float4(0.f, 0.f, 0.f, 0.f);
            float4 vy = vx;
            if (ge < E) {
                const float* xr = xg + (size_t)ge * DIMQ;
                vx = make_float4(xr[u], xr[64 + 3 * u], xr[65 + 3 * u], xr[66 + 3 * u]);
                const float* yr = yg + (size_t)ge * DIMQ;
                vy = make_float4(yr[u], yr[64 + 3 * u], yr[65 + 3 * u], yr[66 + 3 * u]);
            }
            xs[u * 64 + e] = vx;
            ys[u * 64 + e] = vy;
        }
        __syncthreads();

        #pragma unroll 1
        for (int u = 0; u < 64; ++u) {
            __syncthreads();  // guard previous u's wt reads
            {
                const float4* sa = reinterpret_cast<const float4*>(Wa + (size_t)u * 4096);
                const float4* sb = reinterpret_cast<const float4*>(Wb + (size_t)u * 4096);
                const float4* sc = reinterpret_cast<const float4*>(Wc + (size_t)u * 4096);
                const float4* sd = reinterpret_cast<const float4*>(Wd + (size_t)u * 4096);
                #pragma unroll
                for (int k = 0; k < 4; ++k) {
                    const int idx = tid + k * NTHR;    // 0..1023
                    wt4[idx] = sa[idx];
                    float4 t = sb[idx];
                    t.x *= INV_SQRT3; t.y *= INV_SQRT3; t.z *= INV_SQRT3; t.w *= INV_SQRT3;
                    wt4[1024 + idx] = t;               // INV_SQRT3 folded into W110
                    wt4[2048 + idx] = sc[idx];
                    wt4[3072 + idx] = sd[idx];
                }
            }
            __syncthreads();

            float4 xv[4];
            #pragma unroll
            for (int e = 0; e < 4; ++e) xv[e] = xs[u * 64 + te * 4 + e];

            #pragma unroll 2
            for (int v = 0; v < 64; ++v) {
                const float4 b000 = wt4[v * 16 + tw];
                const float4 b110 = wt4[1024 + v * 16 + tw];
                const float4 b011 = wt4[2048 + v * 16 + tw];
                const float4 b101 = wt4[3072 + v * 16 + tw];
                const float4* yrow = ys + v * 64 + te * 4;
                #pragma unroll
                for (int e = 0; e < 4; ++e) {
                    const float4 yv = yrow[e];
                    const float s000 = xv[e].x * yv.x;
                    const float s110 = xv[e].y * yv.y + xv[e].z * yv.z + xv[e].w * yv.w;
                    acc0[e][0] += s000 * b000.x + s110 * b110.x;
                    acc0[e][1] += s000 * b000.y + s110 * b110.y;
                    acc0[e][2] += s000 * b000.z + s110 * b110.z;
                    acc0[e][3] += s000 * b000.w + s110 * b110.w;
                    const float a0 = xv[e].x * yv.y;   // x0 * y1_i
                    const float a1 = xv[e].x * yv.z;
                    const float a2 = xv[e].x * yv.w;
                    const float c0 = xv[e].y * yv.x;   // x1_i * y0
                    const float c1 = xv[e].z * yv.x;
                    const float c2 = xv[e].w * yv.x;
                    acc1[e][0][0] += a0 * b011.x + c0 * b101.x;
                    acc1[e][0][1] += a0 * b011.y + c0 * b101.y;
                    acc1[e][0][2] += a0 * b011.z + c0 * b101.z;
                    acc1[e][0][3] += a0 * b011.w + c0 * b101.w;
                    acc1[e][1][0] += a1 * b011.x + c1 * b101.x;
                    acc1[e][1][1] += a1 * b011.y + c1 * b101.y;
                    acc1[e][1][2] += a1 * b011.z + c1 * b101.z;
                    acc1[e][1][3] += a1 * b011.w + c1 * b101.w;
                    acc1[e][2][0] += a2 * b011.x + c2 * b101.x;
                    acc1[e][2][1] += a2 * b011.y + c2 * b101.y;
                    acc1[e][2][2] += a2 * b011.z + c2 * b101.z;
                    acc1[e][2][3] += a2 * b011.w + c2 * b101.w;
                }
            }
        }
    }

    #pragma unroll
    for (int e = 0; e < 4; ++e) {
        const int ge = e0 + te * 4 + e;
        if (ge < E) {
            float* o = out + (size_t)ge * DIMQ;
            #pragma unroll
            for (int w = 0; w < 4; ++w) {
                const int wg = tw * 4 + w;
                o[wg] = ALPHA0 * acc0[e][w];
                o[64 + wg * 3 + 0] = OUT1S * acc1[e][0][w];
                o[64 + wg * 3 + 1] = OUT1S * acc1[e][1][w];
                o[64 + wg * 3 + 2] = OUT1S * acc1[e][2][w];
            }
        }
    }
}

extern "C" void kernel_launch(void* const* d_in, const int* in_sizes, int n_in,
                              void* d_out, int out_size) {
    const float* e1x    = (const float*)d_in[0];
    const float* e1y    = (const float*)d_in[1];
    const float* e2x    = (const float*)d_in[2];
    const float* e2y    = (const float*)d_in[3];
    const float* W1_000 = (const float*)d_in[4];
    const float* W1_110 = (const float*)d_in[5];
    const float* W1_011 = (const float*)d_in[6];
    const float* W1_101 = (const float*)d_in[7];
    const float* W2_000 = (const float*)d_in[8];
    const float* W2_110 = (const float*)d_in[9];
    const float* W2_011 = (const float*)d_in[10];
    const float* W2_101 = (const float*)d_in[11];
    float* out = (float*)d_out;

    const int E = in_sizes[0] / DIMQ;
    const int grid = (E + M_TILE - 1) / M_TILE;

    cudaFuncSetAttribute(fc_tp_kernel,
                         cudaFuncAttributeMaxDynamicSharedMemorySize, SMEM_BYTES);
    fc_tp_kernel<<<grid, NTHR, SMEM_BYTES>>>(
        e1x, e1y, e2x, e2y,
        W1_000, W1_110, W1_011, W1_101,
        W2_000, W2_110, W2_011, W2_101,
        out, E);
}